// round 7
// baseline (speedup 1.0000x reference)
#include <cuda_runtime.h>
#include <cstdint>

// Conv2d VALID: x[32,64,112,112] f32, w[128,64,3,3] f32 -> out[32,128,110,110] f32
// Implicit GEMM via mma.sync.m16n8k8 tf32.
// Round 6: raw-input-tile staging. Per CTA: M=128 couts, N=128 px (2 oh x 64 ow).
// The 32ch x 4row x 66col input window is staged in smem ONCE per ci-half; all 9
// taps' B fragments are LDS'd directly from it (tap offset folded into address).
// A chunks double-buffered with prefetch. K = 2 ci-halves x 9 taps x 32.

namespace {

constexpr int CIN = 64, COUT = 128, H = 112, W = 112, OH = 110, OW = 110;
constexpr int A_STRIDE = 36;                 // floats per A row (32 + 4 pad)
constexpr int X_KSTRIDE = 264;               // 4*66; 264 % 32 == 8 -> conflict-free B LDS
constexpr int SM_X_FLOATS = 32 * X_KSTRIDE;  // 8448
constexpr int SM_A_FLOATS = 128 * A_STRIDE;  // 4608
constexpr int SM_TOTAL = (SM_X_FLOATS + 2 * SM_A_FLOATS) * 4;  // 70656 B

__device__ float g_A_pre[18 * 4096];  // [kc = h*9+tap][co 128][perm-col 32], tf32

__device__ __forceinline__ float to_tf32(float v) {
    float o;
    asm("cvt.rna.tf32.f32 %0, %1;" : "=f"(o) : "f"(v));
    return o;
}

// perm-col = g*8 + q*2 + e  represents k = g*8 + q + 4*e
__global__ void prep_weights(const float* __restrict__ w) {
    int idx = blockIdx.x * 256 + threadIdx.x;  // 0 .. 73727
    int kc  = idx >> 12;
    int rem = idx & 4095;
    int co  = rem >> 5;
    int col = rem & 31;
    int g = col >> 3, tt = col & 7, q = tt >> 1, e = tt & 1;
    int k  = g * 8 + q + 4 * e;
    int h  = kc / 9;
    int rs = kc - h * 9;
    int ci = h * 32 + k;
    g_A_pre[idx] = to_tf32(w[((size_t)co * CIN + ci) * 9 + rs]);
}

__global__ __launch_bounds__(256, 2)
void conv_mma(const float* __restrict__ x, float* __restrict__ out)
{
    extern __shared__ float sm[];
    float* Xs = sm;                                  // [k*264 + row*66 + col]
    float* Abuf[2] = { sm + SM_X_FLOATS, sm + SM_X_FLOATS + SM_A_FLOATS };

    const int tid  = threadIdx.x;
    const int wid  = tid >> 5;
    const int lane = tid & 31;
    const int wm   = wid >> 2;        // 0..1 (m half)
    const int wn   = wid & 3;         // 0..3 (n quarter)
    const int lr   = lane >> 2;       // 0..7
    const int lq   = lane & 3;        // 0..3

    const int ow0 = blockIdx.x * 64;
    const int oh0 = blockIdx.y * 2;
    const int bb  = blockIdx.z;

    float acc[4][4][4];
#pragma unroll
    for (int i = 0; i < 4; i++)
#pragma unroll
        for (int j = 0; j < 4; j++)
#pragma unroll
            for (int k = 0; k < 4; k++) acc[i][j][k] = 0.0f;

    const float* xb = x + (size_t)bb * CIN * H * W;

    // preload A chunk 0 into buf 0
    {
        const float4* src = (const float4*)g_A_pre;
#pragma unroll
        for (int i = 0; i < 4; ++i) {
            int idx = tid + 256 * i;
            float4 v = src[idx];
            *(float4*)(Abuf[0] + (idx >> 3) * A_STRIDE + (idx & 7) * 4) = v;
        }
    }

    const int osub  = wn >> 1;           // warp's output sub-row (0/1)
    const int cbase = (wn & 1) * 32;     // warp's column base within 64

    for (int h = 0; h < 2; ++h) {
        __syncthreads();   // previous half's compute done before Xs overwrite

        // ---- stage raw input window: 32 ch x 4 rows x 66 cols ----
#pragma unroll
        for (int i = 0; i < 33; ++i) {
            int flat = tid + 256 * i;                 // == k*264 + row*66 + col
            int k    = flat / X_KSTRIDE;
            int rem  = flat - k * X_KSTRIDE;
            int row  = rem / 66;
            int col  = rem - row * 66;
            int iw   = ow0 + col;
            float v  = 0.0f;
            if (iw < W)
                v = xb[((size_t)(h * 32 + k) * H + (oh0 + row)) * W + iw];
            Xs[flat] = v;
        }
        __syncthreads();   // Xs + current A chunk visible

        for (int t = 0; t < 9; ++t) {
            const int kc = h * 9 + t;
            const int r  = t / 3;
            const int s  = t - r * 3;

            // ---- prefetch next A chunk into other buffer ----
            if (kc < 17) {
                const float4* src = (const float4*)(g_A_pre + (kc + 1) * 4096);
                float* dst = Abuf[(kc + 1) & 1];
#pragma unroll
                for (int i = 0; i < 4; ++i) {
                    int idx = tid + 256 * i;
                    float4 v = src[idx];
                    *(float4*)(dst + (idx >> 3) * A_STRIDE + (idx & 7) * 4) = v;
                }
            }

            // ---- compute tap ----
            const float* Ab = Abuf[kc & 1];
            const float* xw = Xs + (osub + r) * 66 + cbase + s;

#pragma unroll
            for (int g = 0; g < 4; ++g) {
                uint32_t a[4][4];
#pragma unroll
                for (int mf = 0; mf < 4; ++mf) {
                    int row = wm * 64 + mf * 16 + lr;
                    float2 v02 = *(const float2*)(Ab + row * A_STRIDE + g * 8 + lq * 2);
                    float2 v13 = *(const float2*)(Ab + (row + 8) * A_STRIDE + g * 8 + lq * 2);
                    a[mf][0] = __float_as_uint(v02.x);
                    a[mf][1] = __float_as_uint(v13.x);
                    a[mf][2] = __float_as_uint(v02.y);
                    a[mf][3] = __float_as_uint(v13.y);
                }
                uint32_t b[4][2];
#pragma unroll
                for (int nf = 0; nf < 4; ++nf) {
                    // conflict-free: bank = (8*lq + lr) covers all 32
                    float v0 = xw[(g * 8 + lq) * X_KSTRIDE + nf * 8 + lr];
                    float v1 = xw[(g * 8 + lq + 4) * X_KSTRIDE + nf * 8 + lr];
                    b[nf][0] = __float_as_uint(to_tf32(v0));
                    b[nf][1] = __float_as_uint(to_tf32(v1));
                }
#pragma unroll
                for (int mf = 0; mf < 4; ++mf)
#pragma unroll
                    for (int nf = 0; nf < 4; ++nf) {
                        asm volatile(
                            "mma.sync.aligned.m16n8k8.row.col.f32.tf32.tf32.f32 "
                            "{%0,%1,%2,%3}, {%4,%5,%6,%7}, {%8,%9}, {%0,%1,%2,%3};"
                            : "+f"(acc[mf][nf][0]), "+f"(acc[mf][nf][1]),
                              "+f"(acc[mf][nf][2]), "+f"(acc[mf][nf][3])
                            : "r"(a[mf][0]), "r"(a[mf][1]), "r"(a[mf][2]), "r"(a[mf][3]),
                              "r"(b[nf][0]), "r"(b[nf][1]));
                    }
            }

            if (t < 8) __syncthreads();   // before next A STS overwrite
        }
    }

    // ---- epilogue: direct STG.64 (even ow, pairs in-bounds) ----
#pragma unroll
    for (int mf = 0; mf < 4; ++mf) {
#pragma unroll
        for (int nf = 0; nf < 4; ++nf) {
            int nglob = wn * 32 + nf * 8 + lq * 2;    // even
            int os    = nglob >> 6;
            int ow    = ow0 + (nglob & 63);
            int oh    = oh0 + os;
            if (ow < OW) {
                int co0 = wm * 64 + mf * 16 + lr;
                float* p0 = out + (((size_t)bb * COUT + co0) * OH + oh) * OW + ow;
                *(float2*)p0 = make_float2(acc[mf][nf][0], acc[mf][nf][1]);
                float* p1 = p0 + (size_t)8 * OH * OW;
                *(float2*)p1 = make_float2(acc[mf][nf][2], acc[mf][nf][3]);
            }
        }
    }
}

} // namespace

extern "C" void kernel_launch(void* const* d_in, const int* in_sizes, int n_in,
                              void* d_out, int out_size)
{
    const float* x = (const float*)d_in[0];
    const float* w = (const float*)d_in[1];
    float* out = (float*)d_out;

    cudaFuncSetAttribute(conv_mma, cudaFuncAttributeMaxDynamicSharedMemorySize, SM_TOTAL);

    prep_weights<<<18 * 4096 / 256, 256>>>(w);

    dim3 grid(2, 55, 32);   // ow tiles, oh pairs, batch
    conv_mma<<<grid, 256, SM_TOTAL>>>(x, out);
}